// round 5
// baseline (speedup 1.0000x reference)
#include <cuda_runtime.h>
#include <cuda_bf16.h>
#include <cstdint>

// Problem constants
constexpr int NB  = 2;    // batch
constexpr int NN  = 768;  // nodes
constexpr int NU  = 64;   // embed dim
constexpr int NK  = 8;    // relation dim
constexpr int NIN = 136;  // 2U + K
constexpr int NSL = 256;  // slot-major row stride (8 slots per lane)
constexpr int MAXE = NN * NN;
constexpr float SLOPE = 0.01f;

// ---------------- device scratch ----------------
__device__ unsigned char g_mask[NN * NN];
__device__ float g_invD[NN];
__device__ int   g_colrows[NN * NN];
__device__ int   g_colcnt[NN];
__device__ int   g_colstart[NN];
__device__ int   g_totE;
__device__ int2  g_eij[MAXE];          // flat edge -> (i, j)
__device__ float g_edgeval[NB * MAXE];
__device__ float g_A   [NB * NN * NSL]; // slot-major
__device__ float g_Base[NB * NN * NSL]; // slot-major
__device__ float g_x1  [NB * NN * NU];

// ---------------- kernel 1: mask + row degree + invD ----------------
__global__ void maskdeg_kernel(const float* __restrict__ rel) {
    int i = blockIdx.x;
    int tid = threadIdx.x;
    int cnt = 0;
    for (int j = tid; j < NN; j += 256) {
        const float4* p = reinterpret_cast<const float4*>(rel + ((size_t)i * NN + j) * NK);
        float4 a = p[0], b = p[1];
        float s = a.x + a.y + a.z + a.w + b.x + b.y + b.z + b.w;
        unsigned char m = (s > 0.0f) ? 1 : 0;
        g_mask[i * NN + j] = m;
        cnt += m;
    }
    #pragma unroll
    for (int o = 16; o > 0; o >>= 1) cnt += __shfl_xor_sync(~0u, cnt, o);
    __shared__ int wsum[8];
    if ((tid & 31) == 0) wsum[tid >> 5] = cnt;
    __syncthreads();
    if (tid == 0) {
        int t = 0;
        #pragma unroll
        for (int w = 0; w < 8; w++) t += wsum[w];
        g_invD[i] = 1.0f / (float)(t > 0 ? t : 1);
    }
}

// ---------------- kernel 2: per-column edge lists (ballot scan, i-ordered) ----------------
__global__ void build_cols_kernel() {
    int j = blockIdx.x;
    int tid = threadIdx.x;          // row i
    int warp = tid >> 5, lane = tid & 31;
    int flag = g_mask[tid * NN + j];
    unsigned bal = __ballot_sync(~0u, flag != 0);
    __shared__ int wcnt[24];
    __shared__ int wpre[25];
    if (lane == 0) wcnt[warp] = __popc(bal);
    __syncthreads();
    if (tid == 0) {
        int acc = 0;
        #pragma unroll
        for (int w = 0; w < 24; w++) { wpre[w] = acc; acc += wcnt[w]; }
        wpre[24] = acc;
        g_colcnt[j] = acc;
    }
    __syncthreads();
    if (flag) {
        int pos = wpre[warp] + __popc(bal & ((1u << lane) - 1u));
        g_colrows[j * NN + pos] = tid;
    }
}

// ---------------- kernel 3: exclusive scan of colcnt ----------------
__global__ void scan_kernel() {
    __shared__ int tmp[NN];
    int t = threadIdx.x;
    int my = g_colcnt[t];
    tmp[t] = my;
    __syncthreads();
    for (int o = 1; o < NN; o <<= 1) {
        int v = (t >= o) ? tmp[t - o] : 0;
        __syncthreads();
        tmp[t] += v;
        __syncthreads();
    }
    g_colstart[t] = tmp[t] - my;
    if (t == NN - 1) g_totE = tmp[t];
}

// ---------------- kernel 4: flatten (warp per column) ----------------
__global__ void flatten_kernel() {
    int gw = blockIdx.x * (blockDim.x >> 5) + (threadIdx.x >> 5);
    if (gw >= NN) return;
    int lane = threadIdx.x & 31;
    int st = g_colstart[gw], c = g_colcnt[gw];
    const int* rows = g_colrows + gw * NN;
    for (int e = lane; e < c; e += 32)
        g_eij[st + e] = make_int2(rows[e], gw);
}

// ---------------- kernel 5: per-node precompute A, Base (slot-major out) ----------------
constexpr int RPB = 8;
__global__ void precompute_kernel(const float* __restrict__ xext, int use_g,
                                  const float* __restrict__ W1,
                                  const float* __restrict__ b1) {
    const float* xp = use_g ? g_x1 : xext;
    __shared__ float sx[RPB][NU];
    int R0 = blockIdx.x * RPB;
    int tid = threadIdx.x;          // 0..159 = logical neuron n
    for (int idx = tid; idx < RPB * NU; idx += 160)
        sx[idx >> 6][idx & 63] = xp[(size_t)R0 * NU + idx];
    __syncthreads();
    int n = tid;
    int slot = ((n & 31) << 3) + (n >> 5);   // lane-major slot
    float a[RPB], bs[RPB];
    #pragma unroll
    for (int r = 0; r < RPB; r++) { a[r] = 0.0f; bs[r] = 0.0f; }
    if (n < NIN) {
        #pragma unroll 4
        for (int u = 0; u < NU; u++) {
            float wa = W1[u * NIN + n];
            float wb = W1[(NU + u) * NIN + n];
            #pragma unroll
            for (int r = 0; r < RPB; r++) {
                a[r]  = fmaf(sx[r][u], wa, a[r]);
                bs[r] = fmaf(sx[r][u], wb, bs[r]);
            }
        }
        float bb = b1[n];
        #pragma unroll
        for (int r = 0; r < RPB; r++) {
            g_A   [(size_t)(R0 + r) * NSL + slot] = a[r];
            g_Base[(size_t)(R0 + r) * NSL + slot] = bs[r] + bb;
        }
    } else {
        #pragma unroll
        for (int r = 0; r < RPB; r++) {
            g_A   [(size_t)(R0 + r) * NSL + slot] = 0.0f;
            g_Base[(size_t)(R0 + r) * NSL + slot] = 0.0f;
        }
    }
    // zero pad slots m=5..7 (96 per node)
    if (tid < 96) {
        int l = tid / 3, m = 5 + tid % 3;
        int sp = (l << 3) + m;
        #pragma unroll
        for (int r = 0; r < RPB; r++) {
            g_A   [(size_t)(R0 + r) * NSL + sp] = 0.0f;
            g_Base[(size_t)(R0 + r) * NSL + sp] = 0.0f;
        }
    }
}

// ---------------- kernel 6: flat edge phase (2 edges x 2 batches, float4 loads) ----------------
__global__ void __launch_bounds__(256, 3) edge_kernel(
    const float* __restrict__ rel,
    const float* __restrict__ W1,      // (136,136); rows 128..135 = rel weights
    const float* __restrict__ w2,      // (136,1)
    const float* __restrict__ b2p)     // (1,)
{
    __shared__ float sW1c[NK * NSL];

    int tid = threadIdx.x, warp = tid >> 5, lane = tid & 31;

    // stage W1c slab slot-major
    for (int idx = tid; idx < NK * NSL; idx += 256) {
        int kk = idx / NSL, sl = idx % NSL;
        int l = sl >> 3, m = sl & 7;
        int n = l + 32 * m;
        sW1c[idx] = (m < 5 && n < NIN) ? W1[(2 * NU + kk) * NIN + n] : 0.0f;
    }
    float w2l[5];
    #pragma unroll
    for (int m = 0; m < 5; m++) {
        int n = lane + 32 * m;
        w2l[m] = (n < NIN) ? w2[n] : 0.0f;
    }
    float b2 = __ldg(b2p);
    __syncthreads();

    int totE = g_totE;
    int nPairs = (totE + 1) >> 1;
    int gw = blockIdx.x * 8 + warp;
    int nw = gridDim.x * 8;
    int lsl = lane << 3;   // this lane's slot base

    for (int P = gw; P < nPairs; P += nw) {
        int e0 = P << 1;
        int  ev[2], iv[2];
        bool valid[2];
        float vdv[2];
        float rv[2][8];
        float h[4][5];      // chain c = s*2 + b

        #pragma unroll
        for (int s = 0; s < 2; s++) {
            int e = e0 + s;
            valid[s] = (e < totE);
            if (!valid[s]) e = totE - 1;
            ev[s] = e;
            int2 eij = g_eij[e];
            int i = eij.x, j = eij.y;
            iv[s] = i;
            vdv[s] = g_invD[i];
            const float4* rp = reinterpret_cast<const float4*>(
                rel + ((size_t)i * NN + j) * NK);
            float4 r0 = rp[0], r1 = rp[1];
            rv[s][0] = r0.x; rv[s][1] = r0.y; rv[s][2] = r0.z; rv[s][3] = r0.w;
            rv[s][4] = r1.x; rv[s][5] = r1.y; rv[s][6] = r1.z; rv[s][7] = r1.w;
            #pragma unroll
            for (int b = 0; b < 2; b++) {
                const float* Ar = g_A    + ((size_t)(b * NN + i)) * NSL + lsl;
                const float* Br = g_Base + ((size_t)(b * NN + j)) * NSL + lsl;
                float4 a4 = *reinterpret_cast<const float4*>(Ar);
                float4 b4 = *reinterpret_cast<const float4*>(Br);
                float  a1 = Ar[4];
                float  b1s = Br[4];
                int c = s * 2 + b;
                h[c][0] = a4.x + b4.x;
                h[c][1] = a4.y + b4.y;
                h[c][2] = a4.z + b4.z;
                h[c][3] = a4.w + b4.w;
                h[c][4] = a1 + b1s;
            }
        }

        // rel-term MLP: per k-step, LDS.128 + LDS.32 serve 20 FMAs
        #pragma unroll
        for (int kk = 0; kk < NK; kk++) {
            const float* wp = sW1c + kk * NSL + lsl;
            float4 w4 = *reinterpret_cast<const float4*>(wp);
            float  w1 = wp[4];
            float w1v[5] = {w4.x, w4.y, w4.z, w4.w, w1};
            #pragma unroll
            for (int c = 0; c < 4; c++)
                #pragma unroll
                for (int m = 0; m < 5; m++)
                    h[c][m] = fmaf(rv[c >> 1][kk], w1v[m], h[c][m]);
        }

        // leaky + dot with w2 (4 independent chains)
        float d[4];
        #pragma unroll
        for (int c = 0; c < 4; c++) {
            float acc = 0.0f;
            #pragma unroll
            for (int m = 0; m < 5; m++) {
                float hv = h[c][m];
                hv = fmaxf(hv, SLOPE * hv);
                acc = fmaf(hv, w2l[m], acc);
            }
            d[c] = acc;
        }
        #pragma unroll
        for (int o = 16; o > 0; o >>= 1) {
            #pragma unroll
            for (int c = 0; c < 4; c++)
                d[c] += __shfl_xor_sync(~0u, d[c], o);
        }
        #pragma unroll
        for (int c = 0; c < 4; c++) {
            int s = c >> 1, b = c & 1;
            float o2 = d[c] + b2;
            o2 = fmaxf(o2, SLOPE * o2);
            float val = o2 * vdv[s];
            if (lane == c && valid[s])
                g_edgeval[b * MAXE + ev[s]] = val;
        }
    }
}

// ---------------- kernel 7: deterministic column reduce + output scale ----------------
__global__ void reduce_scale_kernel(const float* __restrict__ xin_ext,
                                    float* __restrict__ xout_ext,
                                    int use_g_in, int use_g_out) {
    const float* xin  = use_g_in  ? g_x1 : xin_ext;
    float*       xout = use_g_out ? g_x1 : xout_ext;
    int gw = blockIdx.x * (blockDim.x >> 5) + (threadIdx.x >> 5);
    if (gw >= NB * NN) return;
    int lane = threadIdx.x & 31;
    int b = gw / NN, j = gw % NN;
    int st = g_colstart[j], c = g_colcnt[j];
    const float* ev = g_edgeval + (size_t)b * MAXE + st;
    float s = 0.0f;
    for (int e = lane; e < c; e += 32) s += ev[e];
    #pragma unroll
    for (int o = 16; o > 0; o >>= 1) s += __shfl_xor_sync(~0u, s, o);
    size_t base = (size_t)gw * NU;
    xout[base + lane]      = xin[base + lane]      * s;
    xout[base + 32 + lane] = xin[base + 32 + lane] * s;
}

// ---------------- launch ----------------
extern "C" void kernel_launch(void* const* d_in, const int* in_sizes, int n_in,
                              void* d_out, int out_size) {
    const float* seq  = (const float*)d_in[0];
    const float* rel  = (const float*)d_in[1];
    const float* w1_1 = (const float*)d_in[2];
    const float* b1_1 = (const float*)d_in[3];
    const float* w1_2 = (const float*)d_in[4];
    const float* b1_2 = (const float*)d_in[5];
    const float* w2_1 = (const float*)d_in[6];
    const float* b2_1 = (const float*)d_in[7];
    const float* w2_2 = (const float*)d_in[8];
    const float* b2_2 = (const float*)d_in[9];
    float* out = (float*)d_out;

    maskdeg_kernel   <<<NN, 256>>>(rel);
    build_cols_kernel<<<NN, 768>>>();
    scan_kernel      <<<1, NN>>>();
    flatten_kernel   <<<96, 256>>>();

    const int EGRID = 444;
    const int RGRID = (NB * NN + 7) / 8;

    // hop 1: seq -> g_x1
    precompute_kernel  <<<NB * NN / RPB, 160>>>(seq, 0, w1_1, b1_1);
    edge_kernel        <<<EGRID, 256>>>(rel, w1_1, w1_2, b1_2);
    reduce_scale_kernel<<<RGRID, 256>>>(seq, nullptr, 0, 1);

    // hop 2: g_x1 -> out
    precompute_kernel  <<<NB * NN / RPB, 160>>>(nullptr, 1, w2_1, b2_1);
    edge_kernel        <<<EGRID, 256>>>(rel, w2_1, w2_2, b2_2);
    reduce_scale_kernel<<<RGRID, 256>>>(nullptr, out, 1, 0);
}

// round 6
// speedup vs baseline: 1.2495x; 1.2495x over previous
#include <cuda_runtime.h>
#include <cuda_bf16.h>
#include <cstdint>

// Problem constants
constexpr int NB  = 2;    // batch
constexpr int NN  = 768;  // nodes
constexpr int NU  = 64;   // embed dim
constexpr int NK  = 8;    // relation dim
constexpr int NIN = 136;  // 2U + K
constexpr int NPD = 160;  // padded hidden (5 per lane * 32 lanes)
constexpr int MAXE = NN * NN;
constexpr float SLOPE = 0.01f;

// ---------------- device scratch ----------------
__device__ unsigned char g_mask[NN * NN];
__device__ float g_invD[NN];
__device__ int   g_colcnt[NN];
__device__ int   g_colstart[NN];
__device__ int   g_totE;
__device__ int2  g_eij[MAXE];          // flat edge -> (i, j), column-grouped
__device__ float g_edgeval[NB * MAXE];
__device__ float g_A   [NB * NN * NPD];
__device__ float g_Base[NB * NN * NPD];
__device__ float g_x1  [NB * NN * NU];

// ---------------- kernel 1: mask + row degree + invD ----------------
__global__ void maskdeg_kernel(const float* __restrict__ rel) {
    int i = blockIdx.x;
    int tid = threadIdx.x;
    int cnt = 0;
    for (int j = tid; j < NN; j += 256) {
        const float4* p = reinterpret_cast<const float4*>(rel + ((size_t)i * NN + j) * NK);
        float4 a = p[0], b = p[1];
        float s = a.x + a.y + a.z + a.w + b.x + b.y + b.z + b.w;
        unsigned char m = (s > 0.0f) ? 1 : 0;
        g_mask[i * NN + j] = m;
        cnt += m;
    }
    #pragma unroll
    for (int o = 16; o > 0; o >>= 1) cnt += __shfl_xor_sync(~0u, cnt, o);
    __shared__ int wsum[8];
    if ((tid & 31) == 0) wsum[tid >> 5] = cnt;
    __syncthreads();
    if (tid == 0) {
        int t = 0;
        #pragma unroll
        for (int w = 0; w < 8; w++) t += wsum[w];
        g_invD[i] = 1.0f / (float)(t > 0 ? t : 1);
    }
}

// ---------------- kernel 2: per-column counts (ballot) ----------------
__global__ void colcnt_kernel() {
    int j = blockIdx.x;
    int tid = threadIdx.x;          // row i
    int lane = tid & 31;
    int flag = g_mask[tid * NN + j];
    unsigned bal = __ballot_sync(~0u, flag != 0);
    __shared__ int wcnt[24];
    if (lane == 0) wcnt[tid >> 5] = __popc(bal);
    __syncthreads();
    if (tid == 0) {
        int acc = 0;
        #pragma unroll
        for (int w = 0; w < 24; w++) acc += wcnt[w];
        g_colcnt[j] = acc;
    }
}

// ---------------- kernel 3: build compact edge list (fused scan) ----------------
__global__ void build_kernel() {
    int j = blockIdx.x;
    int tid = threadIdx.x;          // row i
    int warp = tid >> 5, lane = tid & 31;

    // phase A: colstart[j] = sum of colcnt[t] for t < j  (L2-hot)
    int cv = (tid < j) ? g_colcnt[tid] : 0;
    #pragma unroll
    for (int o = 16; o > 0; o >>= 1) cv += __shfl_xor_sync(~0u, cv, o);
    __shared__ int wred[24];
    __shared__ int s_st;
    if (lane == 0) wred[warp] = cv;
    __syncthreads();
    if (tid == 0) {
        int st = 0;
        #pragma unroll
        for (int w = 0; w < 24; w++) st += wred[w];
        s_st = st;
        g_colstart[j] = st;
    }

    // phase B: ballot positions within column
    int flag = g_mask[tid * NN + j];
    unsigned bal = __ballot_sync(~0u, flag != 0);
    __shared__ int wcnt[24];
    __shared__ int wpre[25];
    if (lane == 0) wcnt[warp] = __popc(bal);
    __syncthreads();
    if (tid == 0) {
        int acc = 0;
        #pragma unroll
        for (int w = 0; w < 24; w++) { wpre[w] = acc; acc += wcnt[w]; }
        wpre[24] = acc;
        if (j == NN - 1) g_totE = s_st + acc;
    }
    __syncthreads();
    if (flag) {
        int pos = wpre[warp] + __popc(bal & ((1u << lane) - 1u));
        g_eij[s_st + pos] = make_int2(tid, j);
    }
}

// ---------------- kernel 4: per-node precompute A, Base (hop 1) ----------------
constexpr int RPB = 8;
__global__ void precompute_kernel(const float* __restrict__ xp,
                                  const float* __restrict__ W1,
                                  const float* __restrict__ b1) {
    __shared__ float sx[RPB][NU];
    int R0 = blockIdx.x * RPB;
    int tid = threadIdx.x;          // 0..159
    for (int idx = tid; idx < RPB * NU; idx += 160)
        sx[idx >> 6][idx & 63] = xp[(size_t)R0 * NU + idx];
    __syncthreads();
    int n = tid;
    float a[RPB], bs[RPB];
    #pragma unroll
    for (int r = 0; r < RPB; r++) { a[r] = 0.0f; bs[r] = 0.0f; }
    if (n < NIN) {
        #pragma unroll 4
        for (int u = 0; u < NU; u++) {
            float wa = W1[u * NIN + n];
            float wb = W1[(NU + u) * NIN + n];
            #pragma unroll
            for (int r = 0; r < RPB; r++) {
                a[r]  = fmaf(sx[r][u], wa, a[r]);
                bs[r] = fmaf(sx[r][u], wb, bs[r]);
            }
        }
        float bb = b1[n];
        #pragma unroll
        for (int r = 0; r < RPB; r++) {
            g_A   [(size_t)(R0 + r) * NPD + n] = a[r];
            g_Base[(size_t)(R0 + r) * NPD + n] = bs[r] + bb;
        }
    } else if (n < NPD) {
        #pragma unroll
        for (int r = 0; r < RPB; r++) {
            g_A   [(size_t)(R0 + r) * NPD + n] = 0.0f;
            g_Base[(size_t)(R0 + r) * NPD + n] = 0.0f;
        }
    }
}

// ---------------- kernel 4b: fused hop1-reduce + hop2-precompute ----------------
__global__ void __launch_bounds__(256) precompute_fused_kernel(
    const float* __restrict__ seq,     // hop-1 input x0
    const float* __restrict__ W1,
    const float* __restrict__ b1) {
    __shared__ float sx[RPB][NU];
    int R0 = blockIdx.x * RPB;
    int tid = threadIdx.x;             // 256 threads
    int warp = tid >> 5, lane = tid & 31;

    // warp r: reduce hop-1 edgevals for pair p = R0 + r, build x1 = x0 * S
    {
        int p = R0 + warp;
        int b = p / NN, j = p % NN;
        int st = g_colstart[j], c = g_colcnt[j];
        const float* ev = g_edgeval + (size_t)b * MAXE + st;
        float s = 0.0f;
        for (int e = lane; e < c; e += 32) s += ev[e];
        #pragma unroll
        for (int o = 16; o > 0; o >>= 1) s += __shfl_xor_sync(~0u, s, o);
        size_t base = (size_t)p * NU;
        float v0 = seq[base + lane]      * s;
        float v1 = seq[base + 32 + lane] * s;
        sx[warp][lane]      = v0;
        sx[warp][lane + 32] = v1;
        g_x1[base + lane]      = v0;
        g_x1[base + 32 + lane] = v1;
    }
    __syncthreads();

    // GEMM part (160 active threads)
    int n = tid;
    if (n >= NPD) return;
    float a[RPB], bs[RPB];
    #pragma unroll
    for (int r = 0; r < RPB; r++) { a[r] = 0.0f; bs[r] = 0.0f; }
    if (n < NIN) {
        #pragma unroll 4
        for (int u = 0; u < NU; u++) {
            float wa = W1[u * NIN + n];
            float wb = W1[(NU + u) * NIN + n];
            #pragma unroll
            for (int r = 0; r < RPB; r++) {
                a[r]  = fmaf(sx[r][u], wa, a[r]);
                bs[r] = fmaf(sx[r][u], wb, bs[r]);
            }
        }
        float bb = b1[n];
        #pragma unroll
        for (int r = 0; r < RPB; r++) {
            g_A   [(size_t)(R0 + r) * NPD + n] = a[r];
            g_Base[(size_t)(R0 + r) * NPD + n] = bs[r] + bb;
        }
    } else {
        #pragma unroll
        for (int r = 0; r < RPB; r++) {
            g_A   [(size_t)(R0 + r) * NPD + n] = 0.0f;
            g_Base[(size_t)(R0 + r) * NPD + n] = 0.0f;
        }
    }
}

// ---------------- kernel 5: flat edge phase (R4 layout, coalesced scalar loads) ----------------
__global__ void __launch_bounds__(256, 3) edge_kernel(
    const float* __restrict__ rel,
    const float* __restrict__ W1,      // (136,136); rows 128..135 = rel weights
    const float* __restrict__ w2,      // (136,1)
    const float* __restrict__ b2p)     // (1,)
{
    __shared__ float sW1c[NK * NPD];

    int tid = threadIdx.x, warp = tid >> 5, lane = tid & 31;

    for (int idx = tid; idx < NK * NPD; idx += 256) {
        int kk = idx / NPD, n = idx % NPD;
        sW1c[idx] = (n < NIN) ? W1[(2 * NU + kk) * NIN + n] : 0.0f;
    }
    float w2l[5];
    #pragma unroll
    for (int m = 0; m < 5; m++) {
        int n = lane + 32 * m;
        w2l[m] = (n < NIN) ? w2[n] : 0.0f;
    }
    float b2 = __ldg(b2p);
    __syncthreads();

    int totE = g_totE;
    int nPairs = (totE + 1) >> 1;
    int gw = blockIdx.x * 8 + warp;
    int nw = gridDim.x * 8;

    for (int P = gw; P < nPairs; P += nw) {
        int e0 = P << 1;
        int  ev[2];
        bool valid[2];
        float vdv[2];
        float rv[2][8];
        float h[4][5];      // chain c = s*2 + b

        #pragma unroll
        for (int s = 0; s < 2; s++) {
            int e = e0 + s;
            valid[s] = (e < totE);
            if (!valid[s]) e = totE - 1;
            ev[s] = e;
            int2 eij = g_eij[e];
            int i = eij.x, j = eij.y;
            vdv[s] = g_invD[i];
            const float4* rp = reinterpret_cast<const float4*>(
                rel + ((size_t)i * NN + j) * NK);
            float4 r0 = rp[0], r1 = rp[1];
            rv[s][0] = r0.x; rv[s][1] = r0.y; rv[s][2] = r0.z; rv[s][3] = r0.w;
            rv[s][4] = r1.x; rv[s][5] = r1.y; rv[s][6] = r1.z; rv[s][7] = r1.w;
            #pragma unroll
            for (int b = 0; b < 2; b++) {
                const float* Ar = g_A    + ((size_t)(b * NN + i)) * NPD;
                const float* Br = g_Base + ((size_t)(b * NN + j)) * NPD;
                #pragma unroll
                for (int m = 0; m < 5; m++)
                    h[s * 2 + b][m] = Ar[lane + 32 * m] + Br[lane + 32 * m];
            }
        }

        // rel-term MLP: per k-step, 5 broadcast LDS serve 20 FMAs
        #pragma unroll
        for (int kk = 0; kk < NK; kk++) {
            float w1v[5];
            #pragma unroll
            for (int m = 0; m < 5; m++)
                w1v[m] = sW1c[kk * NPD + lane + 32 * m];
            #pragma unroll
            for (int c = 0; c < 4; c++)
                #pragma unroll
                for (int m = 0; m < 5; m++)
                    h[c][m] = fmaf(rv[c >> 1][kk], w1v[m], h[c][m]);
        }

        // leaky + dot with w2 (4 independent chains)
        float d[4];
        #pragma unroll
        for (int c = 0; c < 4; c++) {
            float acc = 0.0f;
            #pragma unroll
            for (int m = 0; m < 5; m++) {
                float hv = h[c][m];
                hv = fmaxf(hv, SLOPE * hv);
                acc = fmaf(hv, w2l[m], acc);
            }
            d[c] = acc;
        }
        #pragma unroll
        for (int o = 16; o > 0; o >>= 1) {
            #pragma unroll
            for (int c = 0; c < 4; c++)
                d[c] += __shfl_xor_sync(~0u, d[c], o);
        }
        #pragma unroll
        for (int c = 0; c < 4; c++) {
            int s = c >> 1, b = c & 1;
            float o2 = d[c] + b2;
            o2 = fmaxf(o2, SLOPE * o2);
            float val = o2 * vdv[s];
            if (lane == c && valid[s])
                g_edgeval[b * MAXE + ev[s]] = val;
        }
    }
}

// ---------------- kernel 6: final column reduce + output scale ----------------
__global__ void reduce_scale_kernel(float* __restrict__ xout) {
    int gw = blockIdx.x * (blockDim.x >> 5) + (threadIdx.x >> 5);
    if (gw >= NB * NN) return;
    int lane = threadIdx.x & 31;
    int b = gw / NN, j = gw % NN;
    int st = g_colstart[j], c = g_colcnt[j];
    const float* ev = g_edgeval + (size_t)b * MAXE + st;
    float s = 0.0f;
    for (int e = lane; e < c; e += 32) s += ev[e];
    #pragma unroll
    for (int o = 16; o > 0; o >>= 1) s += __shfl_xor_sync(~0u, s, o);
    size_t base = (size_t)gw * NU;
    xout[base + lane]      = g_x1[base + lane]      * s;
    xout[base + 32 + lane] = g_x1[base + 32 + lane] * s;
}

// ---------------- launch ----------------
extern "C" void kernel_launch(void* const* d_in, const int* in_sizes, int n_in,
                              void* d_out, int out_size) {
    const float* seq  = (const float*)d_in[0];
    const float* rel  = (const float*)d_in[1];
    const float* w1_1 = (const float*)d_in[2];
    const float* b1_1 = (const float*)d_in[3];
    const float* w1_2 = (const float*)d_in[4];
    const float* b1_2 = (const float*)d_in[5];
    const float* w2_1 = (const float*)d_in[6];
    const float* b2_1 = (const float*)d_in[7];
    const float* w2_2 = (const float*)d_in[8];
    const float* b2_2 = (const float*)d_in[9];
    float* out = (float*)d_out;

    maskdeg_kernel<<<NN, 256>>>(rel);
    colcnt_kernel <<<NN, 768>>>();
    build_kernel  <<<NN, 768>>>();

    const int EGRID = 444;
    const int RGRID = (NB * NN + 7) / 8;

    // hop 1
    precompute_kernel<<<NB * NN / RPB, 160>>>(seq, w1_1, b1_1);
    edge_kernel      <<<EGRID, 256>>>(rel, w1_1, w1_2, b1_2);

    // hop 2 (reduce of hop 1 fused into precompute)
    precompute_fused_kernel<<<NB * NN / RPB, 256>>>(seq, w2_1, b2_1);
    edge_kernel      <<<EGRID, 256>>>(rel, w2_1, w2_2, b2_2);
    reduce_scale_kernel<<<RGRID, 256>>>(out);
}

// round 7
// speedup vs baseline: 1.3621x; 1.0901x over previous
#include <cuda_runtime.h>
#include <cuda_bf16.h>
#include <cstdint>

// Problem constants
constexpr int NB  = 2;    // batch
constexpr int NN  = 768;  // nodes
constexpr int NU  = 64;   // embed dim
constexpr int NK  = 8;    // relation dim
constexpr int NIN = 136;  // 2U + K
constexpr int NPD = 160;  // padded hidden (5 per lane * 32 lanes)
constexpr int MAXE = NN * NN;
constexpr float SLOPE = 0.01f;

// ---------------- device scratch ----------------
__device__ unsigned char g_mask[NN * NN];
__device__ float g_invD[NN];
__device__ int   g_colcnt[NN];
__device__ int   g_colstart[NN];
__device__ int   g_totE;
__device__ int2  g_eij[MAXE];          // flat edge -> (i, j), column-grouped
__device__ float g_edgeval[NB * MAXE];
__device__ float g_A   [NB * NN * NPD];
__device__ float g_Base[NB * NN * NPD];
__device__ float g_x1  [NB * NN * NU];

// ---------------- kernel 1: mask + row degree + invD ----------------
__global__ void maskdeg_kernel(const float* __restrict__ rel) {
    int i = blockIdx.x;
    int tid = threadIdx.x;
    int cnt = 0;
    for (int j = tid; j < NN; j += 256) {
        const float4* p = reinterpret_cast<const float4*>(rel + ((size_t)i * NN + j) * NK);
        float4 a = p[0], b = p[1];
        float s = a.x + a.y + a.z + a.w + b.x + b.y + b.z + b.w;
        unsigned char m = (s > 0.0f) ? 1 : 0;
        g_mask[i * NN + j] = m;
        cnt += m;
    }
    #pragma unroll
    for (int o = 16; o > 0; o >>= 1) cnt += __shfl_xor_sync(~0u, cnt, o);
    __shared__ int wsum[8];
    if ((tid & 31) == 0) wsum[tid >> 5] = cnt;
    __syncthreads();
    if (tid == 0) {
        int t = 0;
        #pragma unroll
        for (int w = 0; w < 8; w++) t += wsum[w];
        g_invD[i] = 1.0f / (float)(t > 0 ? t : 1);
    }
}

// ---------------- kernel 2: per-column counts (ballot) ----------------
__global__ void colcnt_kernel() {
    int j = blockIdx.x;
    int tid = threadIdx.x;          // row i
    int lane = tid & 31;
    int flag = g_mask[tid * NN + j];
    unsigned bal = __ballot_sync(~0u, flag != 0);
    __shared__ int wcnt[24];
    if (lane == 0) wcnt[tid >> 5] = __popc(bal);
    __syncthreads();
    if (tid == 0) {
        int acc = 0;
        #pragma unroll
        for (int w = 0; w < 24; w++) acc += wcnt[w];
        g_colcnt[j] = acc;
    }
}

// ---------------- kernel 3: build compact edge list (fused scan) ----------------
__global__ void build_kernel() {
    int j = blockIdx.x;
    int tid = threadIdx.x;          // row i
    int warp = tid >> 5, lane = tid & 31;

    int cv = (tid < j) ? g_colcnt[tid] : 0;
    #pragma unroll
    for (int o = 16; o > 0; o >>= 1) cv += __shfl_xor_sync(~0u, cv, o);
    __shared__ int wred[24];
    __shared__ int s_st;
    if (lane == 0) wred[warp] = cv;
    __syncthreads();
    if (tid == 0) {
        int st = 0;
        #pragma unroll
        for (int w = 0; w < 24; w++) st += wred[w];
        s_st = st;
        g_colstart[j] = st;
    }

    int flag = g_mask[tid * NN + j];
    unsigned bal = __ballot_sync(~0u, flag != 0);
    __shared__ int wcnt[24];
    __shared__ int wpre[25];
    if (lane == 0) wcnt[warp] = __popc(bal);
    __syncthreads();
    if (tid == 0) {
        int acc = 0;
        #pragma unroll
        for (int w = 0; w < 24; w++) { wpre[w] = acc; acc += wcnt[w]; }
        wpre[24] = acc;
        if (j == NN - 1) g_totE = s_st + acc;
    }
    __syncthreads();
    if (flag) {
        int pos = wpre[warp] + __popc(bal & ((1u << lane) - 1u));
        g_eij[s_st + pos] = make_int2(tid, j);
    }
}

// ---------------- precompute GEMM core (k-split across 2 thread halves) ----------------
constexpr int RPB = 4;   // rows per block
// block = 320 threads: n = tid % 160, kh = tid / 160 (warps uniform in kh)

__device__ __forceinline__ void precompute_core(
    const float (*sx)[NU], float (*spA)[NPD], float (*spB)[NPD],
    int R0, int tid, const float* __restrict__ W1, const float* __restrict__ b1)
{
    int n  = tid % NPD;
    int kh = tid / NPD;
    float a[RPB], bs[RPB];
    #pragma unroll
    for (int r = 0; r < RPB; r++) { a[r] = 0.0f; bs[r] = 0.0f; }
    if (n < NIN) {
        int ub = kh * 32;
        #pragma unroll 4
        for (int u0 = 0; u0 < 32; u0++) {
            int u = ub + u0;
            float wa = W1[u * NIN + n];
            float wb = W1[(NU + u) * NIN + n];
            #pragma unroll
            for (int r = 0; r < RPB; r++) {
                a[r]  = fmaf(sx[r][u], wa, a[r]);
                bs[r] = fmaf(sx[r][u], wb, bs[r]);
            }
        }
    }
    if (kh == 1) {
        #pragma unroll
        for (int r = 0; r < RPB; r++) { spA[r][n] = a[r]; spB[r][n] = bs[r]; }
    }
    __syncthreads();
    if (kh == 0) {
        float bb = (n < NIN) ? b1[n] : 0.0f;
        #pragma unroll
        for (int r = 0; r < RPB; r++) {
            g_A   [(size_t)(R0 + r) * NPD + n] = a[r] + spA[r][n];
            g_Base[(size_t)(R0 + r) * NPD + n] = bs[r] + spB[r][n] + bb;
        }
    }
}

// ---------------- kernel 4: precompute hop 1 ----------------
__global__ void __launch_bounds__(320) precompute_kernel(
    const float* __restrict__ xp,
    const float* __restrict__ W1,
    const float* __restrict__ b1) {
    __shared__ float sx[RPB][NU];
    __shared__ float spA[RPB][NPD];
    __shared__ float spB[RPB][NPD];
    int R0 = blockIdx.x * RPB;
    int tid = threadIdx.x;
    for (int idx = tid; idx < RPB * NU; idx += 320)
        sx[idx >> 6][idx & 63] = xp[(size_t)R0 * NU + idx];
    __syncthreads();
    precompute_core(sx, spA, spB, R0, tid, W1, b1);
}

// ---------------- kernel 4b: fused hop1-reduce + hop2-precompute ----------------
__global__ void __launch_bounds__(320) precompute_fused_kernel(
    const float* __restrict__ seq,
    const float* __restrict__ W1,
    const float* __restrict__ b1) {
    __shared__ float sx[RPB][NU];
    __shared__ float spA[RPB][NPD];
    __shared__ float spB[RPB][NPD];
    int R0 = blockIdx.x * RPB;
    int tid = threadIdx.x;
    int warp = tid >> 5, lane = tid & 31;

    if (warp < RPB) {   // warp r reduces pair R0+r, builds x1 = x0 * S
        int p = R0 + warp;
        int b = p / NN, j = p % NN;
        int st = g_colstart[j], c = g_colcnt[j];
        const float* ev = g_edgeval + (size_t)b * MAXE + st;
        float s = 0.0f;
        for (int e = lane; e < c; e += 32) s += ev[e];
        #pragma unroll
        for (int o = 16; o > 0; o >>= 1) s += __shfl_xor_sync(~0u, s, o);
        size_t base = (size_t)p * NU;
        float v0 = seq[base + lane]      * s;
        float v1 = seq[base + 32 + lane] * s;
        sx[warp][lane]      = v0;
        sx[warp][lane + 32] = v1;
        g_x1[base + lane]      = v0;
        g_x1[base + 32 + lane] = v1;
    }
    __syncthreads();
    precompute_core(sx, spA, spB, R0, tid, W1, b1);
}

// ---------------- kernel 5: flat edge phase ----------------
__global__ void __launch_bounds__(256, 3) edge_kernel(
    const float* __restrict__ rel,
    const float* __restrict__ W1,
    const float* __restrict__ w2,
    const float* __restrict__ b2p)
{
    __shared__ float sW1c[NK * NPD];

    int tid = threadIdx.x, warp = tid >> 5, lane = tid & 31;

    for (int idx = tid; idx < NK * NPD; idx += 256) {
        int kk = idx / NPD, n = idx % NPD;
        sW1c[idx] = (n < NIN) ? W1[(2 * NU + kk) * NIN + n] : 0.0f;
    }
    float w2l[5];
    #pragma unroll
    for (int m = 0; m < 5; m++) {
        int n = lane + 32 * m;
        w2l[m] = (n < NIN) ? w2[n] : 0.0f;
    }
    float b2 = __ldg(b2p);
    __syncthreads();

    int totE = g_totE;
    int nPairs = (totE + 1) >> 1;
    int gw = blockIdx.x * 8 + warp;
    int nw = gridDim.x * 8;

    for (int P = gw; P < nPairs; P += nw) {
        int e0 = P << 1;
        int  ev[2];
        bool valid[2];
        float vdv[2];
        float rv[2][8];
        float h[4][5];      // chain c = s*2 + b

        #pragma unroll
        for (int s = 0; s < 2; s++) {
            int e = e0 + s;
            valid[s] = (e < totE);
            if (!valid[s]) e = totE - 1;
            ev[s] = e;
            int2 eij = g_eij[e];
            int i = eij.x, j = eij.y;
            vdv[s] = g_invD[i];
            const float4* rp = reinterpret_cast<const float4*>(
                rel + ((size_t)i * NN + j) * NK);
            float4 r0 = rp[0], r1 = rp[1];
            rv[s][0] = r0.x; rv[s][1] = r0.y; rv[s][2] = r0.z; rv[s][3] = r0.w;
            rv[s][4] = r1.x; rv[s][5] = r1.y; rv[s][6] = r1.z; rv[s][7] = r1.w;
            #pragma unroll
            for (int b = 0; b < 2; b++) {
                const float* Ar = g_A    + ((size_t)(b * NN + i)) * NPD;
                const float* Br = g_Base + ((size_t)(b * NN + j)) * NPD;
                #pragma unroll
                for (int m = 0; m < 5; m++)
                    h[s * 2 + b][m] = Ar[lane + 32 * m] + Br[lane + 32 * m];
            }
        }

        #pragma unroll
        for (int kk = 0; kk < NK; kk++) {
            float w1v[5];
            #pragma unroll
            for (int m = 0; m < 5; m++)
                w1v[m] = sW1c[kk * NPD + lane + 32 * m];
            #pragma unroll
            for (int c = 0; c < 4; c++)
                #pragma unroll
                for (int m = 0; m < 5; m++)
                    h[c][m] = fmaf(rv[c >> 1][kk], w1v[m], h[c][m]);
        }

        float d[4];
        #pragma unroll
        for (int c = 0; c < 4; c++) {
            float acc = 0.0f;
            #pragma unroll
            for (int m = 0; m < 5; m++) {
                float hv = h[c][m];
                hv = fmaxf(hv, SLOPE * hv);
                acc = fmaf(hv, w2l[m], acc);
            }
            d[c] = acc;
        }
        #pragma unroll
        for (int o = 16; o > 0; o >>= 1) {
            #pragma unroll
            for (int c = 0; c < 4; c++)
                d[c] += __shfl_xor_sync(~0u, d[c], o);
        }
        #pragma unroll
        for (int c = 0; c < 4; c++) {
            int s = c >> 1, b = c & 1;
            float o2 = d[c] + b2;
            o2 = fmaxf(o2, SLOPE * o2);
            float val = o2 * vdv[s];
            if (lane == c && valid[s])
                g_edgeval[b * MAXE + ev[s]] = val;
        }
    }
}

// ---------------- kernel 6: final column reduce + output scale ----------------
__global__ void reduce_scale_kernel(float* __restrict__ xout) {
    int gw = blockIdx.x * (blockDim.x >> 5) + (threadIdx.x >> 5);
    if (gw >= NB * NN) return;
    int lane = threadIdx.x & 31;
    int b = gw / NN, j = gw % NN;
    int st = g_colstart[j], c = g_colcnt[j];
    const float* ev = g_edgeval + (size_t)b * MAXE + st;
    float s = 0.0f;
    for (int e = lane; e < c; e += 32) s += ev[e];
    #pragma unroll
    for (int o = 16; o > 0; o >>= 1) s += __shfl_xor_sync(~0u, s, o);
    size_t base = (size_t)gw * NU;
    xout[base + lane]      = g_x1[base + lane]      * s;
    xout[base + 32 + lane] = g_x1[base + 32 + lane] * s;
}

// ---------------- launch ----------------
extern "C" void kernel_launch(void* const* d_in, const int* in_sizes, int n_in,
                              void* d_out, int out_size) {
    const float* seq  = (const float*)d_in[0];
    const float* rel  = (const float*)d_in[1];
    const float* w1_1 = (const float*)d_in[2];
    const float* b1_1 = (const float*)d_in[3];
    const float* w1_2 = (const float*)d_in[4];
    const float* b1_2 = (const float*)d_in[5];
    const float* w2_1 = (const float*)d_in[6];
    const float* b2_1 = (const float*)d_in[7];
    const float* w2_2 = (const float*)d_in[8];
    const float* b2_2 = (const float*)d_in[9];
    float* out = (float*)d_out;

    maskdeg_kernel<<<NN, 256>>>(rel);
    colcnt_kernel <<<NN, 768>>>();
    build_kernel  <<<NN, 768>>>();

    const int PGRID = NB * NN / RPB;   // 384
    const int EGRID = 444;
    const int RGRID = (NB * NN + 7) / 8;

    // hop 1
    precompute_kernel<<<PGRID, 320>>>(seq, w1_1, b1_1);
    edge_kernel      <<<EGRID, 256>>>(rel, w1_1, w1_2, b1_2);

    // hop 2 (reduce of hop 1 fused into precompute)
    precompute_fused_kernel<<<PGRID, 320>>>(seq, w2_1, b2_1);
    edge_kernel      <<<EGRID, 256>>>(rel, w2_1, w2_2, b2_2);
    reduce_scale_kernel<<<RGRID, 256>>>(out);
}